// round 1
// baseline (speedup 1.0000x reference)
#include <cuda_runtime.h>

#define C6 6
#define MM 4
#define LL 2
#define NSTATE 1296       // 6^4
#define PTOT 2048         // B*N
#define DD 64
#define TPB 224           // 7 warps

// ---------------- device-global precomputed gate storage ----------------
__device__ float  g_BS[2][LL][3][NSTATE];   // [bs1=0/bs2=1][layer][m] 36x36 row-major
__device__ float  g_SQ[LL][MM][36];         // squeeze 6x6
__device__ float  g_DP[LL][MM][36];         // displacement 6x6
__device__ float2 g_DIAG[LL][3][NSTATE];    // fused 4-mode phase tables: rot1, rot2, kerr

// =======================================================================
// Precompute kernel: matrix exponentials of REAL generators + phase tables
//   gate = expm(theta * G), G real:
//     displacement: G = ad - a
//     squeeze:      G = 0.5*(a@a - ad@ad)
//     beamsplitter: G = kron(ad,a) - kron(a,ad)
//   expm via scaling (2^-6) + 12-term Taylor + 6 squarings.
// =======================================================================
__global__ void precompute_kernel(const float* __restrict__ bs1,
                                  const float* __restrict__ sq_r,
                                  const float* __restrict__ bs2,
                                  const float* __restrict__ disp,
                                  const float* __restrict__ rot1,
                                  const float* __restrict__ rot2,
                                  const float* __restrict__ kerr)
{
    __shared__ float A[NSTATE], P[NSTATE], T[NSTATE];
    int tid = threadIdx.x, bd = blockDim.x;
    int b = blockIdx.x;

    if (b < 12) {
        // ---- one 36x36 beamsplitter expm per block ----
        int which = b / 6, r6 = b % 6, l = r6 / 3, m = r6 % 3;
        float theta = (which ? bs2 : bs1)[l * 3 + m];
        for (int i = tid; i < NSTATE; i += bd) {
            int R = i / 36, Cc = i % 36;
            int i1 = R / 6, i2 = R % 6, j1 = Cc / 6, j2 = Cc % 6;
            float g = 0.f;
            if (i1 == j1 + 1 && j2 == i2 + 1) g += sqrtf((float)((j1 + 1) * (i2 + 1)));
            if (j1 == i1 + 1 && i2 == j2 + 1) g -= sqrtf((float)((i1 + 1) * (j2 + 1)));
            float a = theta * g * (1.f / 64.f);
            A[i] = a; P[i] = a; T[i] = a + (R == Cc ? 1.f : 0.f);
        }
        __syncthreads();
        for (int j = 2; j <= 12; j++) {
            float inv = 1.f / (float)j;
            float nv[3]; int cnt = 0;
            for (int i = tid; i < NSTATE; i += bd) {
                int R = i / 36, Cc = i % 36;
                float s = 0.f;
                #pragma unroll 6
                for (int k = 0; k < 36; k++) s += P[R * 36 + k] * A[k * 36 + Cc];
                nv[cnt++] = s * inv;
            }
            __syncthreads();
            cnt = 0;
            for (int i = tid; i < NSTATE; i += bd) { P[i] = nv[cnt]; T[i] += nv[cnt]; cnt++; }
            __syncthreads();
        }
        for (int s = 0; s < 6; s++) {
            float nv[3]; int cnt = 0;
            for (int i = tid; i < NSTATE; i += bd) {
                int R = i / 36, Cc = i % 36;
                float acc = 0.f;
                #pragma unroll 6
                for (int k = 0; k < 36; k++) acc += T[R * 36 + k] * T[k * 36 + Cc];
                nv[cnt++] = acc;
            }
            __syncthreads();
            cnt = 0;
            for (int i = tid; i < NSTATE; i += bd) T[i] = nv[cnt++];
            __syncthreads();
        }
        for (int i = tid; i < NSTATE; i += bd) g_BS[which][l][m][i] = T[i];
    } else {
        // ---- block 12: sixteen 6x6 expms (lockstep) + fused phase tables ----
        bool act = tid < 576;
        int mid = tid / 36, e = tid % 36, r = e / 6, c = e % 6;
        if (act) {
            int l = (mid % 8) / 4, m = mid % 4;
            float theta, g = 0.f;
            if (mid < 8) {  // squeeze
                theta = sq_r[l * 4 + m];
                if (c == r + 2)      g =  0.5f * sqrtf((float)((r + 1) * (r + 2)));
                else if (r == c + 2) g = -0.5f * sqrtf((float)((c + 1) * (c + 2)));
            } else {        // displacement
                theta = disp[l * 4 + m];
                if (r == c + 1)      g =  sqrtf((float)(c + 1));
                else if (c == r + 1) g = -sqrtf((float)(r + 1));
            }
            float a = theta * g * (1.f / 64.f);
            A[tid] = a; P[tid] = a; T[tid] = a + (r == c ? 1.f : 0.f);
        }
        __syncthreads();
        for (int j = 2; j <= 12; j++) {
            float nv = 0.f;
            if (act) {
                float s = 0.f;
                #pragma unroll
                for (int k = 0; k < 6; k++) s += P[mid * 36 + r * 6 + k] * A[mid * 36 + k * 6 + c];
                nv = s / (float)j;
            }
            __syncthreads();
            if (act) { P[tid] = nv; T[tid] += nv; }
            __syncthreads();
        }
        for (int s = 0; s < 6; s++) {
            float nv = 0.f;
            if (act) {
                float acc = 0.f;
                #pragma unroll
                for (int k = 0; k < 6; k++) acc += T[mid * 36 + r * 6 + k] * T[mid * 36 + k * 6 + c];
                nv = acc;
            }
            __syncthreads();
            if (act) T[tid] = nv;
            __syncthreads();
        }
        if (act) {
            int l = (mid % 8) / 4, m = mid % 4;
            if (mid < 8) g_SQ[l][m][e] = T[tid];
            else         g_DP[l][m][e] = T[tid];
        }
        // fused 4-mode diagonal phase tables
        for (int t = tid; t < LL * 3 * NSTATE; t += bd) {
            int l = t / (3 * NSTATE), rem = t % (3 * NSTATE);
            int pass = rem / NSTATE, idx = rem % NSTATE;
            float n3 = (float)(idx % 6), n2 = (float)((idx / 6) % 6),
                  n1 = (float)((idx / 36) % 6), n0 = (float)(idx / 216);
            const float* par = (pass == 0) ? rot1 : (pass == 1) ? rot2 : kerr;
            float ang;
            if (pass < 2)
                ang = par[l*4+0]*n0 + par[l*4+1]*n1 + par[l*4+2]*n2 + par[l*4+3]*n3;
            else
                ang = par[l*4+0]*n0*n0 + par[l*4+1]*n1*n1 + par[l*4+2]*n2*n2 + par[l*4+3]*n3*n3;
            float sn, cs;
            sincosf(ang, &sn, &cs);
            g_DIAG[l][pass][idx] = make_float2(cs, sn);
        }
    }
}

// =======================================================================
// Main kernel: one block per state
// =======================================================================

// two-mode gate (real 36x36) on fibers; out-of-place (ping-pong)
template <int S>
__device__ __forceinline__ void apply2_body(const float* __restrict__ U,
                                            const float* __restrict__ ri,
                                            const float* __restrict__ ii,
                                            float* __restrict__ ro,
                                            float* __restrict__ io, int tid)
{
    if (tid < 216) {
        int g = tid / 36, f = tid - g * 36;
        int base = (f / S) * (36 * S) + (f % S);
        const float* Ur = U + g * 6 * 36;
        float ar[6] = {0,0,0,0,0,0}, ai[6] = {0,0,0,0,0,0};
        #pragma unroll 6
        for (int cd = 0; cd < 36; cd++) {
            float xr = ri[base + cd * S], xi = ii[base + cd * S];
            #pragma unroll
            for (int t = 0; t < 6; t++) {
                float u = Ur[t * 36 + cd];
                ar[t] = fmaf(u, xr, ar[t]);
                ai[t] = fmaf(u, xi, ai[t]);
            }
        }
        #pragma unroll
        for (int t = 0; t < 6; t++) {
            int o = base + (g * 6 + t) * S;
            ro[o] = ar[t]; io[o] = ai[t];
        }
    }
}

// single-mode gate (real 6x6), in-place (fiber-exclusive)
template <int S>
__device__ __forceinline__ void apply1_body(const float* __restrict__ U36,
                                            float* __restrict__ re,
                                            float* __restrict__ im, int tid)
{
    if (tid < 216) {
        int hi = tid / S, lo = tid - hi * S;
        int base = hi * 6 * S + lo;
        float xr[6], xi[6];
        #pragma unroll
        for (int k = 0; k < 6; k++) { xr[k] = re[base + k * S]; xi[k] = im[base + k * S]; }
        #pragma unroll
        for (int r = 0; r < 6; r++) {
            float ar = 0.f, ai = 0.f;
            #pragma unroll
            for (int k = 0; k < 6; k++) {
                float u = U36[r * 6 + k];
                ar = fmaf(u, xr[k], ar);
                ai = fmaf(u, xi[k], ai);
            }
            re[base + r * S] = ar; im[base + r * S] = ai;
        }
    }
}

__global__ __launch_bounds__(TPB) void qnn_kernel(const float* __restrict__ patches,
                                                  const float* __restrict__ enc_w,
                                                  const float* __restrict__ enc_b,
                                                  const float* __restrict__ ro_w,
                                                  const float* __restrict__ ro_b,
                                                  float* __restrict__ out)
{
    __shared__ float sRe[2][NSTATE], sIm[2][NSTATE];
    __shared__ float sU[NSTATE];
    __shared__ float tA[144], tP[144], tT[144];
    __shared__ float sU1[4][36];
    __shared__ float sAlpha[4];
    __shared__ float sD0[4][6];
    __shared__ float sRed[4][8];
    __shared__ float sQ[4];
    __shared__ float sW[5];

    int tid = threadIdx.x;
    int p = blockIdx.x;

    if (tid < 5) sW[tid] = 2.f * sqrtf((float)(tid + 1));

    // ---- per-state displacement amplitudes: alpha = patches_row . enc_w^T + enc_b ----
    if (tid < 128) {
        int m = tid >> 5, lane = tid & 31;
        float v = patches[p * 64 + lane]      * enc_w[m * 64 + lane]
                + patches[p * 64 + lane + 32] * enc_w[m * 64 + lane + 32];
        #pragma unroll
        for (int o = 16; o; o >>= 1) v += __shfl_xor_sync(0xffffffffu, v, o);
        if (lane == 0) sAlpha[m] = v + enc_b[m];
    }
    __syncthreads();

    // ---- Denc = expm(alpha*(ad-a)), 4 matrices in parallel (threads 0..143) ----
    {
        bool act = tid < 144;
        int m = tid / 36, e = tid % 36, r = e / 6, c = e % 6;
        if (act) {
            float g = 0.f;
            if (r == c + 1)      g =  sqrtf((float)(c + 1));
            else if (c == r + 1) g = -sqrtf((float)(r + 1));
            float a = sAlpha[m] * g * (1.f / 64.f);
            tA[tid] = a; tP[tid] = a; tT[tid] = a + (r == c ? 1.f : 0.f);
        }
        __syncthreads();
        for (int j = 2; j <= 12; j++) {
            float nv = 0.f;
            if (act) {
                float s = 0.f;
                #pragma unroll
                for (int k = 0; k < 6; k++) s += tP[m * 36 + r * 6 + k] * tA[m * 36 + k * 6 + c];
                nv = s / (float)j;
            }
            __syncthreads();
            if (act) { tP[tid] = nv; tT[tid] += nv; }
            __syncthreads();
        }
        for (int s = 0; s < 6; s++) {
            float nv = 0.f;
            if (act) {
                float acc = 0.f;
                #pragma unroll
                for (int k = 0; k < 6; k++) acc += tT[m * 36 + r * 6 + k] * tT[m * 36 + k * 6 + c];
                nv = acc;
            }
            __syncthreads();
            if (act) tT[tid] = nv;
            __syncthreads();
        }
        if (act && c == 0) sD0[m][r] = tT[tid];   // only column 0 needed (vacuum input)
    }
    __syncthreads();

    // ---- initial state = outer product of displacement first columns (real) ----
    for (int i = tid; i < NSTATE; i += TPB) {
        int n3 = i % 6, n2 = (i / 6) % 6, n1 = (i / 36) % 6, n0 = i / 216;
        sRe[0][i] = sD0[0][n0] * sD0[1][n1] * sD0[2][n2] * sD0[3][n3];
        sIm[0][i] = 0.f;
    }

    int cur = 0;

    #define STAGE_BS(W, L, M3)                                            \
        __syncthreads();                                                  \
        for (int i = tid; i < NSTATE; i += TPB) sU[i] = g_BS[W][L][M3][i];\
        __syncthreads();

    #define DO_APPLY2(SS)                                                          \
        apply2_body<SS>(sU, sRe[cur], sIm[cur], sRe[cur ^ 1], sIm[cur ^ 1], tid);  \
        cur ^= 1;

    #define DO_DIAG(L, PASS)                                               \
        __syncthreads();                                                   \
        {                                                                  \
            const float2* dg = &g_DIAG[L][PASS][0];                        \
            for (int i = tid; i < NSTATE; i += TPB) {                      \
                float2 ph = dg[i];                                         \
                float rr = sRe[cur][i], im_ = sIm[cur][i];                 \
                sRe[cur][i] = rr * ph.x - im_ * ph.y;                      \
                sIm[cur][i] = rr * ph.y + im_ * ph.x;                      \
            }                                                              \
        }

    #define STAGE_U1(SRC)                                                  \
        __syncthreads();                                                   \
        if (tid < 144) sU1[tid / 36][tid % 36] = ((const float*)(SRC))[tid];\
        __syncthreads();

    #define DO_APPLY1_ALL()                                    \
        apply1_body<216>(sU1[0], sRe[cur], sIm[cur], tid);     \
        __syncthreads();                                       \
        apply1_body<36>(sU1[1], sRe[cur], sIm[cur], tid);      \
        __syncthreads();                                       \
        apply1_body<6>(sU1[2], sRe[cur], sIm[cur], tid);       \
        __syncthreads();                                       \
        apply1_body<1>(sU1[3], sRe[cur], sIm[cur], tid);

    for (int l = 0; l < LL; l++) {
        // interferometer 1
        STAGE_BS(0, l, 0); DO_APPLY2(36);
        STAGE_BS(0, l, 1); DO_APPLY2(6);
        STAGE_BS(0, l, 2); DO_APPLY2(1);
        // rotations 1 (fused over modes)
        DO_DIAG(l, 0);
        // squeezing
        STAGE_U1(g_SQ[l]); DO_APPLY1_ALL();
        // interferometer 2
        STAGE_BS(1, l, 0); DO_APPLY2(36);
        STAGE_BS(1, l, 1); DO_APPLY2(6);
        STAGE_BS(1, l, 2); DO_APPLY2(1);
        // rotations 2
        DO_DIAG(l, 1);
        // displacement
        STAGE_U1(g_DP[l]); DO_APPLY1_ALL();
        // Kerr
        DO_DIAG(l, 2);
    }

    // ---- quadrature expectations  <X_m> = sum 2*sqrt(n+1)*Re(conj(s_n) s_{n+1}) ----
    __syncthreads();
    {
        const float* rr = sRe[cur];
        const float* ii = sIm[cur];
        float q0 = 0.f, q1 = 0.f, q2 = 0.f, q3 = 0.f;
        for (int i = tid; i < NSTATE; i += TPB) {
            int n3 = i % 6, n2 = (i / 6) % 6, n1 = (i / 36) % 6, n0 = i / 216;
            float re0 = rr[i], im0 = ii[i];
            if (n0 < 5) q0 += sW[n0] * (re0 * rr[i + 216] + im0 * ii[i + 216]);
            if (n1 < 5) q1 += sW[n1] * (re0 * rr[i + 36]  + im0 * ii[i + 36]);
            if (n2 < 5) q2 += sW[n2] * (re0 * rr[i + 6]   + im0 * ii[i + 6]);
            if (n3 < 5) q3 += sW[n3] * (re0 * rr[i + 1]   + im0 * ii[i + 1]);
        }
        #pragma unroll
        for (int o = 16; o; o >>= 1) {
            q0 += __shfl_xor_sync(0xffffffffu, q0, o);
            q1 += __shfl_xor_sync(0xffffffffu, q1, o);
            q2 += __shfl_xor_sync(0xffffffffu, q2, o);
            q3 += __shfl_xor_sync(0xffffffffu, q3, o);
        }
        int w = tid >> 5, lane = tid & 31;
        if (lane == 0) { sRed[0][w] = q0; sRed[1][w] = q1; sRed[2][w] = q2; sRed[3][w] = q3; }
    }
    __syncthreads();
    if (tid < 4) {
        float s = 0.f;
        #pragma unroll
        for (int k = 0; k < 7; k++) s += sRed[tid][k];
        sQ[tid] = s;
    }
    __syncthreads();

    // ---- readout: out[p,d] = sum_m quad[m]*ro_w[d,m] + ro_b[d] ----
    if (tid < DD) {
        float o = ro_b[tid];
        #pragma unroll
        for (int m = 0; m < 4; m++) o = fmaf(sQ[m], ro_w[tid * 4 + m], o);
        out[p * DD + tid] = o;
    }
}

// =======================================================================
extern "C" void kernel_launch(void* const* d_in, const int* in_sizes, int n_in,
                              void* d_out, int out_size)
{
    const float* patches = (const float*)d_in[0];
    const float* enc_w   = (const float*)d_in[1];
    const float* enc_b   = (const float*)d_in[2];
    const float* bs1     = (const float*)d_in[3];
    const float* rot1    = (const float*)d_in[4];
    const float* sq_r    = (const float*)d_in[5];
    const float* bs2     = (const float*)d_in[6];
    const float* rot2    = (const float*)d_in[7];
    const float* disp    = (const float*)d_in[8];
    const float* kerr    = (const float*)d_in[9];
    const float* ro_w    = (const float*)d_in[10];
    const float* ro_b    = (const float*)d_in[11];

    precompute_kernel<<<13, 640>>>(bs1, sq_r, bs2, disp, rot1, rot2, kerr);
    qnn_kernel<<<PTOT, TPB>>>(patches, enc_w, enc_b, ro_w, ro_b, (float*)d_out);
}

// round 2
// speedup vs baseline: 1.0944x; 1.0944x over previous
#include <cuda_runtime.h>

#define C6 6
#define MM 4
#define LL 2
#define NSTATE 1296       // 6^4
#define PTOT 2048         // B*N
#define DD 64
#define TPB 224           // 7 warps

// ---------------- device-global precomputed gate storage ----------------
__device__ __align__(16) float  g_BS[2][LL][3][NSTATE];   // [bs1/bs2][layer][m] 36x36 row-major
__device__ __align__(16) float  g_SQ[LL][MM][36];         // squeeze 6x6
__device__ __align__(16) float  g_DP[LL][MM][36];         // displacement 6x6
__device__ __align__(16) float2 g_DIAG[LL][3][NSTATE];    // fused 4-mode phase: rot1, rot2, kerr

// =======================================================================
// Precompute kernel: matrix exponentials of REAL generators + phase tables
// expm via scaling (2^-6) + 12-term Taylor + 6 squarings.
// =======================================================================
__global__ void precompute_kernel(const float* __restrict__ bs1,
                                  const float* __restrict__ sq_r,
                                  const float* __restrict__ bs2,
                                  const float* __restrict__ disp,
                                  const float* __restrict__ rot1,
                                  const float* __restrict__ rot2,
                                  const float* __restrict__ kerr)
{
    __shared__ float A[NSTATE], P[NSTATE], T[NSTATE];
    int tid = threadIdx.x, bd = blockDim.x;
    int b = blockIdx.x;

    if (b < 12) {
        // ---- one 36x36 beamsplitter expm per block ----
        int which = b / 6, r6 = b % 6, l = r6 / 3, m = r6 % 3;
        float theta = (which ? bs2 : bs1)[l * 3 + m];
        for (int i = tid; i < NSTATE; i += bd) {
            int R = i / 36, Cc = i % 36;
            int i1 = R / 6, i2 = R % 6, j1 = Cc / 6, j2 = Cc % 6;
            float g = 0.f;
            if (i1 == j1 + 1 && j2 == i2 + 1) g += sqrtf((float)((j1 + 1) * (i2 + 1)));
            if (j1 == i1 + 1 && i2 == j2 + 1) g -= sqrtf((float)((i1 + 1) * (j2 + 1)));
            float a = theta * g * (1.f / 64.f);
            A[i] = a; P[i] = a; T[i] = a + (R == Cc ? 1.f : 0.f);
        }
        __syncthreads();
        for (int j = 2; j <= 12; j++) {
            float inv = 1.f / (float)j;
            float nv[3]; int cnt = 0;
            for (int i = tid; i < NSTATE; i += bd) {
                int R = i / 36, Cc = i % 36;
                float s = 0.f;
                #pragma unroll 6
                for (int k = 0; k < 36; k++) s += P[R * 36 + k] * A[k * 36 + Cc];
                nv[cnt++] = s * inv;
            }
            __syncthreads();
            cnt = 0;
            for (int i = tid; i < NSTATE; i += bd) { P[i] = nv[cnt]; T[i] += nv[cnt]; cnt++; }
            __syncthreads();
        }
        for (int s = 0; s < 6; s++) {
            float nv[3]; int cnt = 0;
            for (int i = tid; i < NSTATE; i += bd) {
                int R = i / 36, Cc = i % 36;
                float acc = 0.f;
                #pragma unroll 6
                for (int k = 0; k < 36; k++) acc += T[R * 36 + k] * T[k * 36 + Cc];
                nv[cnt++] = acc;
            }
            __syncthreads();
            cnt = 0;
            for (int i = tid; i < NSTATE; i += bd) T[i] = nv[cnt++];
            __syncthreads();
        }
        for (int i = tid; i < NSTATE; i += bd) g_BS[which][l][m][i] = T[i];
    } else {
        // ---- block 12: sixteen 6x6 expms (lockstep) + fused phase tables ----
        bool act = tid < 576;
        int mid = tid / 36, e = tid % 36, r = e / 6, c = e % 6;
        if (act) {
            int l = (mid % 8) / 4, m = mid % 4;
            float theta, g = 0.f;
            if (mid < 8) {  // squeeze
                theta = sq_r[l * 4 + m];
                if (c == r + 2)      g =  0.5f * sqrtf((float)((r + 1) * (r + 2)));
                else if (r == c + 2) g = -0.5f * sqrtf((float)((c + 1) * (c + 2)));
            } else {        // displacement
                theta = disp[l * 4 + m];
                if (r == c + 1)      g =  sqrtf((float)(c + 1));
                else if (c == r + 1) g = -sqrtf((float)(r + 1));
            }
            float a = theta * g * (1.f / 64.f);
            A[tid] = a; P[tid] = a; T[tid] = a + (r == c ? 1.f : 0.f);
        }
        __syncthreads();
        for (int j = 2; j <= 12; j++) {
            float nv = 0.f;
            if (act) {
                float s = 0.f;
                #pragma unroll
                for (int k = 0; k < 6; k++) s += P[mid * 36 + r * 6 + k] * A[mid * 36 + k * 6 + c];
                nv = s / (float)j;
            }
            __syncthreads();
            if (act) { P[tid] = nv; T[tid] += nv; }
            __syncthreads();
        }
        for (int s = 0; s < 6; s++) {
            float nv = 0.f;
            if (act) {
                float acc = 0.f;
                #pragma unroll
                for (int k = 0; k < 6; k++) acc += T[mid * 36 + r * 6 + k] * T[mid * 36 + k * 6 + c];
                nv = acc;
            }
            __syncthreads();
            if (act) T[tid] = nv;
            __syncthreads();
        }
        if (act) {
            int l = (mid % 8) / 4, m = mid % 4;
            if (mid < 8) g_SQ[l][m][e] = T[tid];
            else         g_DP[l][m][e] = T[tid];
        }
        // fused 4-mode diagonal phase tables
        for (int t = tid; t < LL * 3 * NSTATE; t += bd) {
            int l = t / (3 * NSTATE), rem = t % (3 * NSTATE);
            int pass = rem / NSTATE, idx = rem % NSTATE;
            float n3 = (float)(idx % 6), n2 = (float)((idx / 6) % 6),
                  n1 = (float)((idx / 36) % 6), n0 = (float)(idx / 216);
            const float* par = (pass == 0) ? rot1 : (pass == 1) ? rot2 : kerr;
            float ang;
            if (pass < 2)
                ang = par[l*4+0]*n0 + par[l*4+1]*n1 + par[l*4+2]*n2 + par[l*4+3]*n3;
            else
                ang = par[l*4+0]*n0*n0 + par[l*4+1]*n1*n1 + par[l*4+2]*n2*n2 + par[l*4+3]*n3*n3;
            float sn, cs;
            sincosf(ang, &sn, &cs);
            g_DIAG[l][pass][idx] = make_float2(cs, sn);
        }
    }
}

// =======================================================================
// Main kernel: one block per state, state stored as float2 (re,im)
// =======================================================================

// two-mode gate (real 36x36) on fibers; out-of-place (ping-pong)
// Vectorized: state loads LDS.64, U loads LDS.128 broadcasts, 12-element
// register chunks to bound register pressure.
template <int S>
__device__ __forceinline__ void apply2_body(const float* __restrict__ U,
                                            const float2* __restrict__ in,
                                            float2* __restrict__ outp, int tid)
{
    if (tid < 216) {
        int g = tid / 36, f = tid - g * 36;
        int base = (f / S) * (36 * S) + (f % S);
        const float* Ur = U + g * 216;
        float2 acc[6];
        #pragma unroll
        for (int t = 0; t < 6; t++) acc[t] = make_float2(0.f, 0.f);
        #pragma unroll
        for (int c = 0; c < 3; c++) {
            float2 x[12];
            #pragma unroll
            for (int j = 0; j < 12; j++) x[j] = in[base + (c * 12 + j) * S];
            #pragma unroll
            for (int t = 0; t < 6; t++) {
                #pragma unroll
                for (int k = 0; k < 3; k++) {
                    float4 u = *(const float4*)(Ur + t * 36 + c * 12 + k * 4);
                    acc[t].x = fmaf(u.x, x[k*4+0].x, acc[t].x);
                    acc[t].y = fmaf(u.x, x[k*4+0].y, acc[t].y);
                    acc[t].x = fmaf(u.y, x[k*4+1].x, acc[t].x);
                    acc[t].y = fmaf(u.y, x[k*4+1].y, acc[t].y);
                    acc[t].x = fmaf(u.z, x[k*4+2].x, acc[t].x);
                    acc[t].y = fmaf(u.z, x[k*4+2].y, acc[t].y);
                    acc[t].x = fmaf(u.w, x[k*4+3].x, acc[t].x);
                    acc[t].y = fmaf(u.w, x[k*4+3].y, acc[t].y);
                }
            }
        }
        #pragma unroll
        for (int t = 0; t < 6; t++) outp[base + (g * 6 + t) * S] = acc[t];
    }
}

// single-mode gate (real 6x6), in-place (fiber-exclusive, register-staged)
template <int S>
__device__ __forceinline__ void apply1_body(const float* __restrict__ U36,
                                            float2* __restrict__ st, int tid)
{
    if (tid < 216) {
        int hi = tid / S, lo = tid - hi * S;
        int base = hi * 6 * S + lo;
        float u[36];
        #pragma unroll
        for (int q = 0; q < 9; q++) {
            float4 v = *(const float4*)(U36 + q * 4);
            u[q*4] = v.x; u[q*4+1] = v.y; u[q*4+2] = v.z; u[q*4+3] = v.w;
        }
        float2 x[6];
        #pragma unroll
        for (int k = 0; k < 6; k++) x[k] = st[base + k * S];
        #pragma unroll
        for (int r = 0; r < 6; r++) {
            float ar = 0.f, ai = 0.f;
            #pragma unroll
            for (int k = 0; k < 6; k++) {
                ar = fmaf(u[r*6+k], x[k].x, ar);
                ai = fmaf(u[r*6+k], x[k].y, ai);
            }
            st[base + r * S] = make_float2(ar, ai);
        }
    }
}

__global__ __launch_bounds__(TPB) void qnn_kernel(const float* __restrict__ patches,
                                                  const float* __restrict__ enc_w,
                                                  const float* __restrict__ enc_b,
                                                  const float* __restrict__ ro_w,
                                                  const float* __restrict__ ro_b,
                                                  float* __restrict__ out)
{
    __shared__ __align__(16) float2 sSt[2][NSTATE];
    __shared__ __align__(16) float sU[NSTATE];
    __shared__ __align__(16) float sU1[4][36];
    __shared__ float tA[144], tP[144], tT[144];
    __shared__ float sAlpha[4];
    __shared__ float sD0[4][6];
    __shared__ float sRed[4][8];
    __shared__ float sQ[4];
    __shared__ float sW[5];

    int tid = threadIdx.x;
    int p = blockIdx.x;

    if (tid < 5) sW[tid] = 2.f * sqrtf((float)(tid + 1));

    // ---- per-state displacement amplitudes: alpha = patches_row . enc_w^T + enc_b ----
    if (tid < 128) {
        int m = tid >> 5, lane = tid & 31;
        float v = patches[p * 64 + lane]      * enc_w[m * 64 + lane]
                + patches[p * 64 + lane + 32] * enc_w[m * 64 + lane + 32];
        #pragma unroll
        for (int o = 16; o; o >>= 1) v += __shfl_xor_sync(0xffffffffu, v, o);
        if (lane == 0) sAlpha[m] = v + enc_b[m];
    }
    __syncthreads();

    // ---- Denc = expm(alpha*(ad-a)), 4 matrices in parallel (threads 0..143) ----
    {
        bool act = tid < 144;
        int m = tid / 36, e = tid % 36, r = e / 6, c = e % 6;
        if (act) {
            float g = 0.f;
            if (r == c + 1)      g =  sqrtf((float)(c + 1));
            else if (c == r + 1) g = -sqrtf((float)(r + 1));
            float a = sAlpha[m] * g * (1.f / 64.f);
            tA[tid] = a; tP[tid] = a; tT[tid] = a + (r == c ? 1.f : 0.f);
        }
        __syncthreads();
        for (int j = 2; j <= 12; j++) {
            float nv = 0.f;
            if (act) {
                float s = 0.f;
                #pragma unroll
                for (int k = 0; k < 6; k++) s += tP[m * 36 + r * 6 + k] * tA[m * 36 + k * 6 + c];
                nv = s / (float)j;
            }
            __syncthreads();
            if (act) { tP[tid] = nv; tT[tid] += nv; }
            __syncthreads();
        }
        for (int s = 0; s < 6; s++) {
            float nv = 0.f;
            if (act) {
                float acc = 0.f;
                #pragma unroll
                for (int k = 0; k < 6; k++) acc += tT[m * 36 + r * 6 + k] * tT[m * 36 + k * 6 + c];
                nv = acc;
            }
            __syncthreads();
            if (act) tT[tid] = nv;
            __syncthreads();
        }
        if (act && c == 0) sD0[m][r] = tT[tid];   // only column 0 needed (vacuum input)
    }
    __syncthreads();

    // ---- initial state = outer product of displacement first columns (real) ----
    for (int i = tid; i < NSTATE; i += TPB) {
        int n3 = i % 6, n2 = (i / 6) % 6, n1 = (i / 36) % 6, n0 = i / 216;
        sSt[0][i] = make_float2(sD0[0][n0] * sD0[1][n1] * sD0[2][n2] * sD0[3][n3], 0.f);
    }

    int cur = 0;

    #define STAGE_BS(W, L, M3)                                             \
        __syncthreads();                                                   \
        {                                                                  \
            const float4* src = (const float4*)g_BS[W][L][M3];             \
            float4* dst = (float4*)sU;                                     \
            for (int i = tid; i < 324; i += TPB) dst[i] = src[i];          \
        }                                                                  \
        __syncthreads();

    #define DO_APPLY2(SS)                                                       \
        apply2_body<SS>(sU, sSt[cur], sSt[cur ^ 1], tid);                       \
        cur ^= 1;

    #define DO_DIAG(L, PASS)                                               \
        __syncthreads();                                                   \
        {                                                                  \
            const float2* dg = &g_DIAG[L][PASS][0];                        \
            float2* st = sSt[cur];                                         \
            for (int i = tid; i < NSTATE; i += TPB) {                      \
                float2 ph = dg[i];                                         \
                float2 s = st[i];                                          \
                st[i] = make_float2(s.x * ph.x - s.y * ph.y,               \
                                    s.x * ph.y + s.y * ph.x);              \
            }                                                              \
        }

    #define STAGE_U1(SRC)                                                  \
        __syncthreads();                                                   \
        if (tid < 36) ((float4*)sU1)[tid] = ((const float4*)(SRC))[tid];   \
        __syncthreads();

    #define DO_APPLY1_ALL()                                    \
        apply1_body<216>(sU1[0], sSt[cur], tid);               \
        __syncthreads();                                       \
        apply1_body<36>(sU1[1], sSt[cur], tid);                \
        __syncthreads();                                       \
        apply1_body<6>(sU1[2], sSt[cur], tid);                 \
        __syncthreads();                                       \
        apply1_body<1>(sU1[3], sSt[cur], tid);

    for (int l = 0; l < LL; l++) {
        // interferometer 1
        STAGE_BS(0, l, 0); DO_APPLY2(36);
        STAGE_BS(0, l, 1); DO_APPLY2(6);
        STAGE_BS(0, l, 2); DO_APPLY2(1);
        // rotations 1 (fused over modes)
        DO_DIAG(l, 0);
        // squeezing
        STAGE_U1(g_SQ[l]); DO_APPLY1_ALL();
        // interferometer 2
        STAGE_BS(1, l, 0); DO_APPLY2(36);
        STAGE_BS(1, l, 1); DO_APPLY2(6);
        STAGE_BS(1, l, 2); DO_APPLY2(1);
        // rotations 2
        DO_DIAG(l, 1);
        // displacement
        STAGE_U1(g_DP[l]); DO_APPLY1_ALL();
        // Kerr
        DO_DIAG(l, 2);
    }

    // ---- quadrature expectations  <X_m> = sum 2*sqrt(n+1)*Re(conj(s_n) s_{n+1}) ----
    __syncthreads();
    {
        const float2* st = sSt[cur];
        float q0 = 0.f, q1 = 0.f, q2 = 0.f, q3 = 0.f;
        for (int i = tid; i < NSTATE; i += TPB) {
            int n3 = i % 6, n2 = (i / 6) % 6, n1 = (i / 36) % 6, n0 = i / 216;
            float2 s0 = st[i];
            if (n0 < 5) { float2 s = st[i + 216]; q0 += sW[n0] * (s0.x * s.x + s0.y * s.y); }
            if (n1 < 5) { float2 s = st[i + 36];  q1 += sW[n1] * (s0.x * s.x + s0.y * s.y); }
            if (n2 < 5) { float2 s = st[i + 6];   q2 += sW[n2] * (s0.x * s.x + s0.y * s.y); }
            if (n3 < 5) { float2 s = st[i + 1];   q3 += sW[n3] * (s0.x * s.x + s0.y * s.y); }
        }
        #pragma unroll
        for (int o = 16; o; o >>= 1) {
            q0 += __shfl_xor_sync(0xffffffffu, q0, o);
            q1 += __shfl_xor_sync(0xffffffffu, q1, o);
            q2 += __shfl_xor_sync(0xffffffffu, q2, o);
            q3 += __shfl_xor_sync(0xffffffffu, q3, o);
        }
        int w = tid >> 5, lane = tid & 31;
        if (lane == 0) { sRed[0][w] = q0; sRed[1][w] = q1; sRed[2][w] = q2; sRed[3][w] = q3; }
    }
    __syncthreads();
    if (tid < 4) {
        float s = 0.f;
        #pragma unroll
        for (int k = 0; k < 7; k++) s += sRed[tid][k];
        sQ[tid] = s;
    }
    __syncthreads();

    // ---- readout: out[p,d] = sum_m quad[m]*ro_w[d,m] + ro_b[d] ----
    if (tid < DD) {
        float o = ro_b[tid];
        #pragma unroll
        for (int m = 0; m < 4; m++) o = fmaf(sQ[m], ro_w[tid * 4 + m], o);
        out[p * DD + tid] = o;
    }
}

// =======================================================================
extern "C" void kernel_launch(void* const* d_in, const int* in_sizes, int n_in,
                              void* d_out, int out_size)
{
    const float* patches = (const float*)d_in[0];
    const float* enc_w   = (const float*)d_in[1];
    const float* enc_b   = (const float*)d_in[2];
    const float* bs1     = (const float*)d_in[3];
    const float* rot1    = (const float*)d_in[4];
    const float* sq_r    = (const float*)d_in[5];
    const float* bs2     = (const float*)d_in[6];
    const float* rot2    = (const float*)d_in[7];
    const float* disp    = (const float*)d_in[8];
    const float* kerr    = (const float*)d_in[9];
    const float* ro_w    = (const float*)d_in[10];
    const float* ro_b    = (const float*)d_in[11];

    precompute_kernel<<<13, 640>>>(bs1, sq_r, bs2, disp, rot1, rot2, kerr);
    qnn_kernel<<<PTOT, TPB>>>(patches, enc_w, enc_b, ro_w, ro_b, (float*)d_out);
}